// round 3
// baseline (speedup 1.0000x reference)
#include <cuda_runtime.h>
#include <math.h>

#define BATCH 4
#define DIM   256
#define MID   128
#define HH    128
#define WW    128
#define EPSV  1e-5f

// ---------------- scratch (device globals; no runtime allocation) ----------
static const size_t SZ_MID = (size_t)BATCH * MID * HH * WW;   // 8,388,608
static const size_t SZ_DIM = (size_t)BATCH * DIM * HH * WW;   // 16,777,216

__device__ float g_relu1[SZ_MID];
__device__ float g_relu2[SZ_MID];
__device__ float g_pool [SZ_MID];
__device__ float g_skip [SZ_DIM];
__device__ float g_y    [SZ_DIM];
__device__ float g_colmax[(size_t)BATCH * MID * WW];
__device__ float g_rowmax[(size_t)BATCH * MID * HH];
__device__ float g_scale[1024];
__device__ float g_shift[1024];

// ---------------- BN fold: scale = g*rsqrt(v+eps), shift = b - m*scale -----
__global__ void bnprep_kernel(const float* __restrict__ g, const float* __restrict__ b,
                              const float* __restrict__ m, const float* __restrict__ v,
                              float* __restrict__ sc, float* __restrict__ sh, int n)
{
    int i = blockIdx.x * blockDim.x + threadIdx.x;
    if (i < n) {
        float inv = rsqrtf(v[i] + EPSV);
        float s = g[i] * inv;
        sc[i] = s;
        sh[i] = b[i] - m[i] * s;
    }
}

// ---------------- 3x3 conv, pad=1, fused BN (+optional skip add, +ReLU) ----
// Tile: 32 output channels x (8 rows x 16 cols). 256 threads.
// Thread owns 4 co x 4 consecutive px. KC=4 input channels per smem stage.
__global__ __launch_bounds__(256, 2)
void conv3x3_kernel(const float* __restrict__ in, int CIN,
                    const float* __restrict__ wgt,      // [COUT, CIN, 3, 3]
                    const float* __restrict__ scale,
                    const float* __restrict__ shift,
                    const float* __restrict__ skip,     // may be null
                    float* __restrict__ out, int COUT, int do_relu)
{
    const int TH = 8, TW = 16, KC = 4;
    __shared__ float s_in[KC][10][19];   // padded stride 19 to cut bank conflicts
    __shared__ float s_w [KC][32][9];

    const int tiles_w = WW / TW;                       // 8
    const int tile = blockIdx.x;                       // 0..127
    const int th0  = (tile / tiles_w) * TH;
    const int tw0  = (tile % tiles_w) * TW;
    const int co_base = blockIdx.y * 32;
    const int b = blockIdx.z;

    const int tid    = threadIdx.x;
    const int co_sub = tid >> 5;          // 0..7 -> 4 co each
    const int pg     = tid & 31;
    const int r      = pg >> 2;           // 0..7
    const int cg     = (pg & 3) * 4;      // 0,4,8,12

    float acc[4][4];
#pragma unroll
    for (int i = 0; i < 4; i++)
#pragma unroll
        for (int j = 0; j < 4; j++) acc[i][j] = 0.f;

    const float* in_b = in + (size_t)b * CIN * HH * WW;

    for (int c0 = 0; c0 < CIN; c0 += KC) {
        // stage input patch KC x 10 x 18 (zero-padded at image edge)
        for (int idx = tid; idx < KC * 10 * 18; idx += 256) {
            int kc  = idx / 180;
            int rem = idx % 180;
            int iy  = rem / 18;
            int ix  = rem % 18;
            int gy  = th0 + iy - 1;
            int gx  = tw0 + ix - 1;
            float v = 0.f;
            if (gy >= 0 && gy < HH && gx >= 0 && gx < WW)
                v = in_b[((size_t)(c0 + kc) * HH + gy) * WW + gx];
            s_in[kc][iy][ix] = v;
        }
        // stage weights KC x 32 x 9
        for (int idx = tid; idx < KC * 32 * 9; idx += 256) {
            int kc  = idx / (32 * 9);
            int rem = idx % (32 * 9);
            int co  = rem / 9;
            int k   = rem % 9;
            s_w[kc][co][k] = wgt[((size_t)(co_base + co) * CIN + (c0 + kc)) * 9 + k];
        }
        __syncthreads();

#pragma unroll
        for (int kc = 0; kc < KC; kc++) {
            float xr[3][6];
#pragma unroll
            for (int dr = 0; dr < 3; dr++)
#pragma unroll
                for (int dc = 0; dc < 6; dc++)
                    xr[dr][dc] = s_in[kc][r + dr][cg + dc];
#pragma unroll
            for (int c4 = 0; c4 < 4; c4++) {
                float w9[9];
#pragma unroll
                for (int k = 0; k < 9; k++) w9[k] = s_w[kc][co_sub * 4 + c4][k];
#pragma unroll
                for (int px = 0; px < 4; px++) {
#pragma unroll
                    for (int kh = 0; kh < 3; kh++)
#pragma unroll
                        for (int kw = 0; kw < 3; kw++)
                            acc[c4][px] = fmaf(xr[kh][px + kw], w9[kh * 3 + kw], acc[c4][px]);
                }
            }
        }
        __syncthreads();
    }

#pragma unroll
    for (int c4 = 0; c4 < 4; c4++) {
        int co = co_base + co_sub * 4 + c4;
        float sc = scale[co], sh = shift[co];
#pragma unroll
        for (int px = 0; px < 4; px++) {
            int gy = th0 + r;
            int gx = tw0 + cg + px;
            size_t oidx = (((size_t)b * COUT + co) * HH + gy) * WW + gx;
            float v = acc[c4][px] * sc + sh;
            if (skip) v += skip[oidx];
            if (do_relu) v = fmaxf(v, 0.f);
            out[oidx] = v;
        }
    }
}

// ---------------- 1x1 conv + BN (no relu) ----------------------------------
// Tile: 32 co x 128 contiguous pixels. 256 threads, 4 co x 4 px per thread.
__global__ __launch_bounds__(256, 2)
void conv1x1_kernel(const float* __restrict__ in, int CIN,
                    const float* __restrict__ wgt,    // [COUT, CIN]
                    const float* __restrict__ scale,
                    const float* __restrict__ shift,
                    float* __restrict__ out, int COUT)
{
    const int KC = 8, TPX = 128;
    __shared__ float s_x[KC][TPX];
    __shared__ float s_w[KC][32];

    const int px0     = blockIdx.x * TPX;   // pixel offset within one image
    const int co_base = blockIdx.y * 32;
    const int b       = blockIdx.z;
    const int tid     = threadIdx.x;
    const int co_sub  = tid >> 5;
    const int pgl     = tid & 31;

    float acc[4][4];
#pragma unroll
    for (int i = 0; i < 4; i++)
#pragma unroll
        for (int j = 0; j < 4; j++) acc[i][j] = 0.f;

    const float* in_b = in + (size_t)b * CIN * HH * WW;

    for (int c0 = 0; c0 < CIN; c0 += KC) {
        for (int idx = tid; idx < KC * TPX; idx += 256) {
            int kc = idx / TPX, p = idx % TPX;
            s_x[kc][p] = in_b[(size_t)(c0 + kc) * HH * WW + px0 + p];
        }
        for (int idx = tid; idx < KC * 32; idx += 256) {
            int kc = idx / 32, co = idx % 32;
            s_w[kc][co] = wgt[(size_t)(co_base + co) * CIN + c0 + kc];
        }
        __syncthreads();
#pragma unroll
        for (int kc = 0; kc < KC; kc++) {
            float xv[4];
#pragma unroll
            for (int p = 0; p < 4; p++) xv[p] = s_x[kc][pgl * 4 + p];
#pragma unroll
            for (int c4 = 0; c4 < 4; c4++) {
                float wv = s_w[kc][co_sub * 4 + c4];
#pragma unroll
                for (int p = 0; p < 4; p++) acc[c4][p] = fmaf(xv[p], wv, acc[c4][p]);
            }
        }
        __syncthreads();
    }

#pragma unroll
    for (int c4 = 0; c4 < 4; c4++) {
        int co = co_base + co_sub * 4 + c4;
        float sc = scale[co], sh = shift[co];
#pragma unroll
        for (int p = 0; p < 4; p++) {
            size_t oidx = ((size_t)b * COUT + co) * (HH * WW) + px0 + pgl * 4 + p;
            out[oidx] = acc[c4][p] * sc + sh;
        }
    }
}

// ---------------- pools: cummax(rev) then cummax == global max broadcast ---
__global__ void colmax_kernel(const float* __restrict__ in, float* __restrict__ outv)
{
    // in: [B*MID, H, W]; out: [B*MID, W] = max over H
    int idx = blockIdx.x * blockDim.x + threadIdx.x;
    if (idx >= BATCH * MID * WW) return;
    int w  = idx % WW;
    int bc = idx / WW;
    const float* p = in + (size_t)bc * HH * WW + w;
    float m = -INFINITY;
#pragma unroll 4
    for (int h = 0; h < HH; h++) m = fmaxf(m, p[(size_t)h * WW]);
    outv[idx] = m;
}

__global__ void rowmax_kernel(const float* __restrict__ in, float* __restrict__ outv)
{
    // in: [B*MID*H, W]; out: [B*MID, H] = max over W. One warp per row.
    int row  = blockIdx.x * (blockDim.x / 32) + (threadIdx.x >> 5);
    int lane = threadIdx.x & 31;
    if (row >= BATCH * MID * HH) return;
    const float* p = in + (size_t)row * WW;
    float m = -INFINITY;
    for (int w = lane; w < WW; w += 32) m = fmaxf(m, p[w]);
#pragma unroll
    for (int off = 16; off; off >>= 1) m = fmaxf(m, __shfl_xor_sync(0xFFFFFFFFu, m, off));
    if (lane == 0) outv[row] = m;
}

__global__ void bcast_add_kernel(const float* __restrict__ colm,
                                 const float* __restrict__ rowm,
                                 float* __restrict__ outp)
{
    size_t idx = (size_t)blockIdx.x * blockDim.x + threadIdx.x;
    if (idx >= SZ_MID) return;
    int    w  = (int)(idx % WW);
    size_t t  = idx / WW;
    int    h  = (int)(t % HH);
    size_t bc = t / HH;
    outp[idx] = colm[bc * WW + w] + rowm[bc * HH + h];
}

// ---------------- launch -----------------------------------------------------
extern "C" void kernel_launch(void* const* d_in, const int* in_sizes, int n_in,
                              void* d_out, int out_size)
{
    const float* x    = (const float*)d_in[0];
    const float* p1_w = (const float*)d_in[1];
    const float* p1_g = (const float*)d_in[2];
    const float* p1_b = (const float*)d_in[3];
    const float* p1_m = (const float*)d_in[4];
    const float* p1_v = (const float*)d_in[5];
    const float* p2_w = (const float*)d_in[6];
    const float* p2_g = (const float*)d_in[7];
    const float* p2_b = (const float*)d_in[8];
    const float* p2_m = (const float*)d_in[9];
    const float* p2_v = (const float*)d_in[10];
    const float* p_w  = (const float*)d_in[11];
    const float* p_g  = (const float*)d_in[12];
    const float* p_b  = (const float*)d_in[13];
    const float* p_m  = (const float*)d_in[14];
    const float* p_v  = (const float*)d_in[15];
    const float* c1_w = (const float*)d_in[16];
    const float* c1_g = (const float*)d_in[17];
    const float* c1_b = (const float*)d_in[18];
    const float* c1_m = (const float*)d_in[19];
    const float* c1_v = (const float*)d_in[20];
    const float* c2_w = (const float*)d_in[21];
    const float* c2_g = (const float*)d_in[22];
    const float* c2_b = (const float*)d_in[23];
    const float* c2_m = (const float*)d_in[24];
    const float* c2_v = (const float*)d_in[25];

    float *relu1, *relu2, *pool, *skip, *y, *colm, *rowm, *sc, *sh;
    cudaGetSymbolAddress((void**)&relu1, g_relu1);
    cudaGetSymbolAddress((void**)&relu2, g_relu2);
    cudaGetSymbolAddress((void**)&pool,  g_pool);
    cudaGetSymbolAddress((void**)&skip,  g_skip);
    cudaGetSymbolAddress((void**)&y,     g_y);
    cudaGetSymbolAddress((void**)&colm,  g_colmax);
    cudaGetSymbolAddress((void**)&rowm,  g_rowmax);
    cudaGetSymbolAddress((void**)&sc,    g_scale);
    cudaGetSymbolAddress((void**)&sh,    g_shift);

    // BN folds: offsets p1:0, p2:128, p:256, c1:512, c2:768
    bnprep_kernel<<<1, 128>>>(p1_g, p1_b, p1_m, p1_v, sc + 0,   sh + 0,   MID);
    bnprep_kernel<<<1, 128>>>(p2_g, p2_b, p2_m, p2_v, sc + 128, sh + 128, MID);
    bnprep_kernel<<<1, 256>>>(p_g,  p_b,  p_m,  p_v,  sc + 256, sh + 256, DIM);
    bnprep_kernel<<<1, 256>>>(c1_g, c1_b, c1_m, c1_v, sc + 512, sh + 512, DIM);
    bnprep_kernel<<<1, 256>>>(c2_g, c2_b, c2_m, c2_v, sc + 768, sh + 768, DIM);

    dim3 blk(256);
    dim3 g_mid(128, MID / 32, BATCH);   // 3x3 convs producing 128 channels
    dim3 g_dim(128, DIM / 32, BATCH);   // 3x3 convs producing 256 channels

    // branch convs
    conv3x3_kernel<<<g_mid, blk>>>(x, DIM, p1_w, sc + 0,   sh + 0,   nullptr, relu1, MID, 1);
    conv3x3_kernel<<<g_mid, blk>>>(x, DIM, p2_w, sc + 128, sh + 128, nullptr, relu2, MID, 1);

    // composed directional pools == global max along H / W, broadcast-added
    colmax_kernel<<<(BATCH * MID * WW + 255) / 256, 256>>>(relu1, colm);
    rowmax_kernel<<<(BATCH * MID * HH) / 8, 256>>>(relu2, rowm);
    bcast_add_kernel<<<(unsigned)((SZ_MID + 255) / 256), 256>>>(colm, rowm, pool);

    // skip: 1x1 conv + BN
    dim3 g_c1(HH * WW / 128, DIM / 32, BATCH);
    conv1x1_kernel<<<g_c1, blk>>>(x, DIM, c1_w, sc + 512, sh + 512, skip, DIM);

    // merge conv + BN + skip-add + ReLU
    conv3x3_kernel<<<g_dim, blk>>>(pool, MID, p_w, sc + 256, sh + 256, skip, y, DIM, 1);

    // final conv + BN + ReLU -> output
    conv3x3_kernel<<<g_dim, blk>>>(y, DIM, c2_w, sc + 768, sh + 768, nullptr, (float*)d_out, DIM, 1);
}

// round 4
// speedup vs baseline: 1.0039x; 1.0039x over previous
#include <cuda_runtime.h>
#include <math.h>

#define BATCH 4
#define DIM   256
#define MID   128
#define HH    128
#define WW    128
#define EPSV  1e-5f

// ---------------- scratch (device globals; no runtime allocation) ----------
static const size_t SZ_MID = (size_t)BATCH * MID * HH * WW;   // 8,388,608
static const size_t SZ_DIM = (size_t)BATCH * DIM * HH * WW;   // 16,777,216

__device__ float g_relu1[SZ_MID];
__device__ float g_relu2[SZ_MID];
__device__ float g_pool [SZ_MID];
__device__ float g_skip [SZ_DIM];
__device__ float g_y    [SZ_DIM];
__device__ float g_colmax[(size_t)BATCH * MID * WW];
__device__ float g_rowmax[(size_t)BATCH * MID * HH];
__device__ float g_scale[1024];
__device__ float g_shift[1024];

// ---------------- BN fold: scale = g*rsqrt(v+eps), shift = b - m*scale -----
__global__ void bnprep_kernel(const float* __restrict__ g, const float* __restrict__ b,
                              const float* __restrict__ m, const float* __restrict__ v,
                              float* __restrict__ sc, float* __restrict__ sh, int n)
{
    int i = blockIdx.x * blockDim.x + threadIdx.x;
    if (i < n) {
        float inv = rsqrtf(v[i] + EPSV);
        float s = g[i] * inv;
        sc[i] = s;
        sh[i] = b[i] - m[i] * s;
    }
}

// ---------------- 3x3 conv, pad=1, fused BN (+optional skip add, +ReLU) ----
// Tile: 32 output channels x (8 rows x 16 cols). 256 threads.
// Thread owns 4 co x 4 consecutive px. KC=4 input channels per smem stage.
__global__ __launch_bounds__(256, 2)
void conv3x3_kernel(const float* __restrict__ in, int CIN,
                    const float* __restrict__ wgt,      // [COUT, CIN, 3, 3]
                    const float* __restrict__ scale,
                    const float* __restrict__ shift,
                    const float* __restrict__ skip,     // may be null
                    float* __restrict__ out, int COUT, int do_relu)
{
    const int TH = 8, TW = 16, KC = 4;
    __shared__ float s_in[KC][10][19];   // padded stride 19 to cut bank conflicts
    __shared__ float s_w [KC][32][9];

    const int tiles_w = WW / TW;                       // 8
    const int tile = blockIdx.x;                       // 0..127
    const int th0  = (tile / tiles_w) * TH;
    const int tw0  = (tile % tiles_w) * TW;
    const int co_base = blockIdx.y * 32;
    const int b = blockIdx.z;

    const int tid    = threadIdx.x;
    const int co_sub = tid >> 5;          // 0..7 -> 4 co each
    const int pg     = tid & 31;
    const int r      = pg >> 2;           // 0..7
    const int cg     = (pg & 3) * 4;      // 0,4,8,12

    float acc[4][4];
#pragma unroll
    for (int i = 0; i < 4; i++)
#pragma unroll
        for (int j = 0; j < 4; j++) acc[i][j] = 0.f;

    const float* in_b = in + (size_t)b * CIN * HH * WW;

    for (int c0 = 0; c0 < CIN; c0 += KC) {
        // stage input patch KC x 10 x 18 (zero-padded at image edge)
        for (int idx = tid; idx < KC * 10 * 18; idx += 256) {
            int kc  = idx / 180;
            int rem = idx % 180;
            int iy  = rem / 18;
            int ix  = rem % 18;
            int gy  = th0 + iy - 1;
            int gx  = tw0 + ix - 1;
            float v = 0.f;
            if (gy >= 0 && gy < HH && gx >= 0 && gx < WW)
                v = in_b[((size_t)(c0 + kc) * HH + gy) * WW + gx];
            s_in[kc][iy][ix] = v;
        }
        // stage weights KC x 32 x 9
        for (int idx = tid; idx < KC * 32 * 9; idx += 256) {
            int kc  = idx / (32 * 9);
            int rem = idx % (32 * 9);
            int co  = rem / 9;
            int k   = rem % 9;
            s_w[kc][co][k] = wgt[((size_t)(co_base + co) * CIN + (c0 + kc)) * 9 + k];
        }
        __syncthreads();

#pragma unroll
        for (int kc = 0; kc < KC; kc++) {
            float xr[3][6];
#pragma unroll
            for (int dr = 0; dr < 3; dr++)
#pragma unroll
                for (int dc = 0; dc < 6; dc++)
                    xr[dr][dc] = s_in[kc][r + dr][cg + dc];
#pragma unroll
            for (int c4 = 0; c4 < 4; c4++) {
                float w9[9];
#pragma unroll
                for (int k = 0; k < 9; k++) w9[k] = s_w[kc][co_sub * 4 + c4][k];
#pragma unroll
                for (int px = 0; px < 4; px++) {
#pragma unroll
                    for (int kh = 0; kh < 3; kh++)
#pragma unroll
                        for (int kw = 0; kw < 3; kw++)
                            acc[c4][px] = fmaf(xr[kh][px + kw], w9[kh * 3 + kw], acc[c4][px]);
                }
            }
        }
        __syncthreads();
    }

#pragma unroll
    for (int c4 = 0; c4 < 4; c4++) {
        int co = co_base + co_sub * 4 + c4;
        float sc = scale[co], sh = shift[co];
#pragma unroll
        for (int px = 0; px < 4; px++) {
            int gy = th0 + r;
            int gx = tw0 + cg + px;
            size_t oidx = (((size_t)b * COUT + co) * HH + gy) * WW + gx;
            float v = acc[c4][px] * sc + sh;
            if (skip) v += skip[oidx];
            if (do_relu) v = fmaxf(v, 0.f);
            out[oidx] = v;
        }
    }
}

// ---------------- 1x1 conv + BN (no relu) ----------------------------------
// Tile: 32 co x 128 contiguous pixels. 256 threads, 4 co x 4 px per thread.
__global__ __launch_bounds__(256, 2)
void conv1x1_kernel(const float* __restrict__ in, int CIN,
                    const float* __restrict__ wgt,    // [COUT, CIN]
                    const float* __restrict__ scale,
                    const float* __restrict__ shift,
                    float* __restrict__ out, int COUT)
{
    const int KC = 8, TPX = 128;
    __shared__ float s_x[KC][TPX];
    __shared__ float s_w[KC][32];

    const int px0     = blockIdx.x * TPX;   // pixel offset within one image
    const int co_base = blockIdx.y * 32;
    const int b       = blockIdx.z;
    const int tid     = threadIdx.x;
    const int co_sub  = tid >> 5;
    const int pgl     = tid & 31;

    float acc[4][4];
#pragma unroll
    for (int i = 0; i < 4; i++)
#pragma unroll
        for (int j = 0; j < 4; j++) acc[i][j] = 0.f;

    const float* in_b = in + (size_t)b * CIN * HH * WW;

    for (int c0 = 0; c0 < CIN; c0 += KC) {
        for (int idx = tid; idx < KC * TPX; idx += 256) {
            int kc = idx / TPX, p = idx % TPX;
            s_x[kc][p] = in_b[(size_t)(c0 + kc) * HH * WW + px0 + p];
        }
        for (int idx = tid; idx < KC * 32; idx += 256) {
            int kc = idx / 32, co = idx % 32;
            s_w[kc][co] = wgt[(size_t)(co_base + co) * CIN + c0 + kc];
        }
        __syncthreads();
#pragma unroll
        for (int kc = 0; kc < KC; kc++) {
            float xv[4];
#pragma unroll
            for (int p = 0; p < 4; p++) xv[p] = s_x[kc][pgl * 4 + p];
#pragma unroll
            for (int c4 = 0; c4 < 4; c4++) {
                float wv = s_w[kc][co_sub * 4 + c4];
#pragma unroll
                for (int p = 0; p < 4; p++) acc[c4][p] = fmaf(xv[p], wv, acc[c4][p]);
            }
        }
        __syncthreads();
    }

#pragma unroll
    for (int c4 = 0; c4 < 4; c4++) {
        int co = co_base + co_sub * 4 + c4;
        float sc = scale[co], sh = shift[co];
#pragma unroll
        for (int p = 0; p < 4; p++) {
            size_t oidx = ((size_t)b * COUT + co) * (HH * WW) + px0 + pgl * 4 + p;
            out[oidx] = acc[c4][p] * sc + sh;
        }
    }
}

// ---------------- pools: cummax(rev) then cummax == global max broadcast ---
__global__ void colmax_kernel(const float* __restrict__ in, float* __restrict__ outv)
{
    // in: [B*MID, H, W]; out: [B*MID, W] = max over H
    int idx = blockIdx.x * blockDim.x + threadIdx.x;
    if (idx >= BATCH * MID * WW) return;
    int w  = idx % WW;
    int bc = idx / WW;
    const float* p = in + (size_t)bc * HH * WW + w;
    float m = -INFINITY;
#pragma unroll 4
    for (int h = 0; h < HH; h++) m = fmaxf(m, p[(size_t)h * WW]);
    outv[idx] = m;
}

__global__ void rowmax_kernel(const float* __restrict__ in, float* __restrict__ outv)
{
    // in: [B*MID*H, W]; out: [B*MID, H] = max over W. One warp per row.
    int row  = blockIdx.x * (blockDim.x / 32) + (threadIdx.x >> 5);
    int lane = threadIdx.x & 31;
    if (row >= BATCH * MID * HH) return;
    const float* p = in + (size_t)row * WW;
    float m = -INFINITY;
    for (int w = lane; w < WW; w += 32) m = fmaxf(m, p[w]);
#pragma unroll
    for (int off = 16; off; off >>= 1) m = fmaxf(m, __shfl_xor_sync(0xFFFFFFFFu, m, off));
    if (lane == 0) outv[row] = m;
}

__global__ void bcast_add_kernel(const float* __restrict__ colm,
                                 const float* __restrict__ rowm,
                                 float* __restrict__ outp)
{
    size_t idx = (size_t)blockIdx.x * blockDim.x + threadIdx.x;
    if (idx >= SZ_MID) return;
    int    w  = (int)(idx % WW);
    size_t t  = idx / WW;
    int    h  = (int)(t % HH);
    size_t bc = t / HH;
    outp[idx] = colm[bc * WW + w] + rowm[bc * HH + h];
}

// ---------------- launch -----------------------------------------------------
extern "C" void kernel_launch(void* const* d_in, const int* in_sizes, int n_in,
                              void* d_out, int out_size)
{
    const float* x    = (const float*)d_in[0];
    const float* p1_w = (const float*)d_in[1];
    const float* p1_g = (const float*)d_in[2];
    const float* p1_b = (const float*)d_in[3];
    const float* p1_m = (const float*)d_in[4];
    const float* p1_v = (const float*)d_in[5];
    const float* p2_w = (const float*)d_in[6];
    const float* p2_g = (const float*)d_in[7];
    const float* p2_b = (const float*)d_in[8];
    const float* p2_m = (const float*)d_in[9];
    const float* p2_v = (const float*)d_in[10];
    const float* p_w  = (const float*)d_in[11];
    const float* p_g  = (const float*)d_in[12];
    const float* p_b  = (const float*)d_in[13];
    const float* p_m  = (const float*)d_in[14];
    const float* p_v  = (const float*)d_in[15];
    const float* c1_w = (const float*)d_in[16];
    const float* c1_g = (const float*)d_in[17];
    const float* c1_b = (const float*)d_in[18];
    const float* c1_m = (const float*)d_in[19];
    const float* c1_v = (const float*)d_in[20];
    const float* c2_w = (const float*)d_in[21];
    const float* c2_g = (const float*)d_in[22];
    const float* c2_b = (const float*)d_in[23];
    const float* c2_m = (const float*)d_in[24];
    const float* c2_v = (const float*)d_in[25];

    float *relu1, *relu2, *pool, *skip, *y, *colm, *rowm, *sc, *sh;
    cudaGetSymbolAddress((void**)&relu1, g_relu1);
    cudaGetSymbolAddress((void**)&relu2, g_relu2);
    cudaGetSymbolAddress((void**)&pool,  g_pool);
    cudaGetSymbolAddress((void**)&skip,  g_skip);
    cudaGetSymbolAddress((void**)&y,     g_y);
    cudaGetSymbolAddress((void**)&colm,  g_colmax);
    cudaGetSymbolAddress((void**)&rowm,  g_rowmax);
    cudaGetSymbolAddress((void**)&sc,    g_scale);
    cudaGetSymbolAddress((void**)&sh,    g_shift);

    // BN folds: offsets p1:0, p2:128, p:256, c1:512, c2:768
    bnprep_kernel<<<1, 128>>>(p1_g, p1_b, p1_m, p1_v, sc + 0,   sh + 0,   MID);
    bnprep_kernel<<<1, 128>>>(p2_g, p2_b, p2_m, p2_v, sc + 128, sh + 128, MID);
    bnprep_kernel<<<1, 256>>>(p_g,  p_b,  p_m,  p_v,  sc + 256, sh + 256, DIM);
    bnprep_kernel<<<1, 256>>>(c1_g, c1_b, c1_m, c1_v, sc + 512, sh + 512, DIM);
    bnprep_kernel<<<1, 256>>>(c2_g, c2_b, c2_m, c2_v, sc + 768, sh + 768, DIM);

    dim3 blk(256);
    dim3 g_mid(128, MID / 32, BATCH);   // 3x3 convs producing 128 channels
    dim3 g_dim(128, DIM / 32, BATCH);   // 3x3 convs producing 256 channels

    // branch convs
    conv3x3_kernel<<<g_mid, blk>>>(x, DIM, p1_w, sc + 0,   sh + 0,   nullptr, relu1, MID, 1);
    conv3x3_kernel<<<g_mid, blk>>>(x, DIM, p2_w, sc + 128, sh + 128, nullptr, relu2, MID, 1);

    // composed directional pools == global max along H / W, broadcast-added
    colmax_kernel<<<(BATCH * MID * WW + 255) / 256, 256>>>(relu1, colm);
    rowmax_kernel<<<(BATCH * MID * HH) / 8, 256>>>(relu2, rowm);
    bcast_add_kernel<<<(unsigned)((SZ_MID + 255) / 256), 256>>>(colm, rowm, pool);

    // skip: 1x1 conv + BN
    dim3 g_c1(HH * WW / 128, DIM / 32, BATCH);
    conv1x1_kernel<<<g_c1, blk>>>(x, DIM, c1_w, sc + 512, sh + 512, skip, DIM);

    // merge conv + BN + skip-add + ReLU
    conv3x3_kernel<<<g_dim, blk>>>(pool, MID, p_w, sc + 256, sh + 256, skip, y, DIM, 1);

    // final conv + BN + ReLU -> output
    conv3x3_kernel<<<g_dim, blk>>>(y, DIM, c2_w, sc + 768, sh + 768, nullptr, (float*)d_out, DIM, 1);
}

// round 6
// speedup vs baseline: 3.1372x; 3.1249x over previous
#include <cuda_runtime.h>
#include <math.h>
#include <stdint.h>

#define BATCH 4
#define DIM   256
#define MID   128
#define HH    128
#define WW    128
#define EPSV  1e-5f

// ---------------- scratch (device globals; no runtime allocation) ----------
static const size_t SZ_MID = (size_t)BATCH * MID * HH * WW;   // 8,388,608
static const size_t SZ_DIM = (size_t)BATCH * DIM * HH * WW;   // 16,777,216

__device__ float g_relu1[SZ_MID];
__device__ float g_relu2[SZ_MID];
__device__ float g_pool [SZ_MID];
__device__ float g_skip [SZ_DIM];
__device__ float g_y    [SZ_DIM];
__device__ float g_colmax[(size_t)BATCH * MID * WW];
__device__ float g_rowmax[(size_t)BATCH * MID * HH];
__device__ float g_scale[1024];
__device__ float g_shift[1024];
// transposed weights: [k][ci][co]  (ci runs over full CIN, co contiguous)
__device__ float g_wt1 [9 * MID * DIM];    // p1  [9][256][128]
__device__ float g_wt2 [9 * MID * DIM];    // p2
__device__ float g_wtp [9 * DIM * MID];    // merge [9][128][256]
__device__ float g_wtc1[DIM * DIM];        // skip 1x1 [1][256][256]
__device__ float g_wtc2[9 * DIM * DIM];    // final

// ---------------- helpers ----------------------------------------------------
__device__ __forceinline__ uint32_t tf32b(float x) {
    uint32_t r; asm("cvt.rn.tf32.f32 %0, %1;" : "=r"(r) : "f"(x)); return r;
}

__device__ __forceinline__ void mma_tf32(float* c, const uint32_t* a, const uint32_t* b) {
    asm volatile("mma.sync.aligned.m16n8k8.row.col.f32.tf32.tf32.f32 "
        "{%0,%1,%2,%3}, {%4,%5,%6,%7}, {%8,%9}, {%0,%1,%2,%3};"
        : "+f"(c[0]), "+f"(c[1]), "+f"(c[2]), "+f"(c[3])
        : "r"(a[0]), "r"(a[1]), "r"(a[2]), "r"(a[3]), "r"(b[0]), "r"(b[1]));
}

// smem row stride in floats: 136 (136 % 32 == 8 -> all fragment LDS patterns
// hit 32 distinct banks: bank = (8*k + idx) mod 32 over the warp)
#define SSTR 136

// ---------------- BN fold ---------------------------------------------------
__global__ void bnprep_kernel(const float* __restrict__ g, const float* __restrict__ b,
                              const float* __restrict__ m, const float* __restrict__ v,
                              float* __restrict__ sc, float* __restrict__ sh, int n)
{
    int i = blockIdx.x * blockDim.x + threadIdx.x;
    if (i < n) {
        float inv = rsqrtf(v[i] + EPSV);
        float s = g[i] * inv;
        sc[i] = s;
        sh[i] = b[i] - m[i] * s;
    }
}

// ------------- weight transpose: [CO,CI,KK] view -> [k][ci][co] -------------
__global__ void wtrans_kernel(const float* __restrict__ w, float* __restrict__ wt,
                              int COUT, int CIN, int KK)
{
    size_t n = (size_t)COUT * CIN * KK;
    for (size_t o = (size_t)blockIdx.x * blockDim.x + threadIdx.x; o < n;
         o += (size_t)gridDim.x * blockDim.x) {
        int co = (int)(o % COUT);
        size_t t = o / COUT;
        int ci = (int)(t % CIN);
        int k  = (int)(t / CIN);
        wt[o] = w[((size_t)co * CIN + ci) * KK + k];
    }
}

// ---------------- tf32 mma.sync implicit-GEMM conv --------------------------
// CTA: 128 co x 128 px (one output image row). 256 threads.
// Producers: tid<128 build B [32ci][128px], tid>=128 build A [32ci][128co].
// Consumers: 8 warps, warp (wm=wid&1, wn=wid>>1) owns 64co x 32px.
__global__ __launch_bounds__(256, 2)
void convmma_kernel(const float* __restrict__ in, int CIN,
                    const float* __restrict__ wtT, int KK,      // 9 or 1
                    const float* __restrict__ scale,
                    const float* __restrict__ shift,
                    const float* __restrict__ skip,             // may be null
                    float* __restrict__ out, int COUT, int do_relu)
{
    __shared__ float sA[32 * SSTR];
    __shared__ float sB[32 * SSTR];

    const int tid  = threadIdx.x;
    const int wid  = tid >> 5;
    const int lane = tid & 31;
    const int y       = blockIdx.x;
    const int co_base = blockIdx.y * 128;
    const int b       = blockIdx.z;
    const int nCB = CIN / 32;

    const int wm = wid & 1;    // 0..1 -> co half (64)
    const int wn = wid >> 1;   // 0..3 -> px quarter (32)

    float acc[4][4][4];
#pragma unroll
    for (int i = 0; i < 4; i++)
#pragma unroll
        for (int j = 0; j < 4; j++)
#pragma unroll
            for (int q = 0; q < 4; q++) acc[i][j][q] = 0.f;

    const size_t cstr = (size_t)HH * WW;

    for (int cb = 0; cb < nCB; cb++) {
        for (int k = 0; k < KK; k++) {
            const int dy = (KK == 9) ? (k / 3 - 1) : 0;
            const int dx = (KK == 9) ? (k % 3 - 1) : 0;
            const int yy = y + dy;
            if (yy < 0 || yy >= HH) continue;   // whole stage contributes zero

            __syncthreads();   // previous stage fully consumed

            if (tid < 128) {
                // B: sB[ci][px], tf32-converted, zero outside image
                const int px = tid;
                const int xx = px + dx;
                const bool xv = (xx >= 0) && (xx < WW);
                const float* src = in + (((size_t)b * CIN + cb * 32) * HH + yy) * WW + xx;
                uint32_t* dst = (uint32_t*)sB + px;
#pragma unroll
                for (int c = 0; c < 32; c++) {
                    uint32_t v = xv ? tf32b(src[(size_t)c * cstr]) : 0u;
                    dst[c * SSTR] = v;
                }
            } else {
                // A: sA[ci][co] from wtT[k][cb*32+ci][co_base..]
                const int u   = tid - 128;
                const int ci  = u >> 2;
                const int coq = (u & 3) * 32;
                const float* wr = wtT + ((size_t)k * CIN + cb * 32 + ci) * COUT + co_base + coq;
                uint32_t* dst = (uint32_t*)sA + ci * SSTR + coq;
#pragma unroll
                for (int j = 0; j < 8; j++) {
                    float4 f = *(const float4*)(wr + j * 4);
                    dst[j * 4 + 0] = tf32b(f.x);
                    dst[j * 4 + 1] = tf32b(f.y);
                    dst[j * 4 + 2] = tf32b(f.z);
                    dst[j * 4 + 3] = tf32b(f.w);
                }
            }
            __syncthreads();

            // consume: 4 k-steps of m16n8k8
#pragma unroll
            for (int ks = 0; ks < 4; ks++) {
                const int k0 = ks * 8 + (lane & 3);
                const uint32_t* pa0 = (const uint32_t*)sA + k0 * SSTR;
                const uint32_t* pa4 = pa0 + 4 * SSTR;
                const uint32_t* pb0 = (const uint32_t*)sB + k0 * SSTR;
                const uint32_t* pb4 = pb0 + 4 * SSTR;

                uint32_t af[4][4], bf[4][2];
#pragma unroll
                for (int mt = 0; mt < 4; mt++) {
                    const int r0 = wm * 64 + mt * 16 + (lane >> 2);
                    af[mt][0] = pa0[r0];
                    af[mt][1] = pa0[r0 + 8];
                    af[mt][2] = pa4[r0];
                    af[mt][3] = pa4[r0 + 8];
                }
#pragma unroll
                for (int nt = 0; nt < 4; nt++) {
                    const int c0 = wn * 32 + nt * 8 + (lane >> 2);
                    bf[nt][0] = pb0[c0];
                    bf[nt][1] = pb4[c0];
                }
#pragma unroll
                for (int mt = 0; mt < 4; mt++)
#pragma unroll
                    for (int nt = 0; nt < 4; nt++)
                        mma_tf32(acc[mt][nt], af[mt], bf[nt]);
            }
        }
    }

    // epilogue: BN (+skip) (+relu), direct register write-out
#pragma unroll
    for (int mt = 0; mt < 4; mt++) {
        const int r0 = co_base + wm * 64 + mt * 16 + (lane >> 2);
        const int r1 = r0 + 8;
        const float sc0 = scale[r0], sh0 = shift[r0];
        const float sc1 = scale[r1], sh1 = shift[r1];
        const size_t ob0 = ((size_t)(b * COUT + r0) * HH + y) * WW;
        const size_t ob1 = ((size_t)(b * COUT + r1) * HH + y) * WW;
#pragma unroll
        for (int nt = 0; nt < 4; nt++) {
            const int c = wn * 32 + nt * 8 + 2 * (lane & 3);
            float2 v0, v1;
            v0.x = acc[mt][nt][0] * sc0 + sh0;
            v0.y = acc[mt][nt][1] * sc0 + sh0;
            v1.x = acc[mt][nt][2] * sc1 + sh1;
            v1.y = acc[mt][nt][3] * sc1 + sh1;
            if (skip) {
                float2 s0 = *(const float2*)(skip + ob0 + c);
                float2 s1 = *(const float2*)(skip + ob1 + c);
                v0.x += s0.x; v0.y += s0.y;
                v1.x += s1.x; v1.y += s1.y;
            }
            if (do_relu) {
                v0.x = fmaxf(v0.x, 0.f); v0.y = fmaxf(v0.y, 0.f);
                v1.x = fmaxf(v1.x, 0.f); v1.y = fmaxf(v1.y, 0.f);
            }
            *(float2*)(out + ob0 + c) = v0;
            *(float2*)(out + ob1 + c) = v1;
        }
    }
}

// ---------------- pools: composed cummax pairs == global max broadcast ------
__global__ void colmax_kernel(const float* __restrict__ in, float* __restrict__ outv)
{
    int idx = blockIdx.x * blockDim.x + threadIdx.x;
    if (idx >= BATCH * MID * WW) return;
    int w  = idx % WW;
    int bc = idx / WW;
    const float* p = in + (size_t)bc * HH * WW + w;
    float m = -INFINITY;
#pragma unroll 4
    for (int h = 0; h < HH; h++) m = fmaxf(m, p[(size_t)h * WW]);
    outv[idx] = m;
}

__global__ void rowmax_kernel(const float* __restrict__ in, float* __restrict__ outv)
{
    int row  = blockIdx.x * (blockDim.x / 32) + (threadIdx.x >> 5);
    int lane = threadIdx.x & 31;
    if (row >= BATCH * MID * HH) return;
    const float* p = in + (size_t)row * WW;
    float m = -INFINITY;
    for (int w = lane; w < WW; w += 32) m = fmaxf(m, p[w]);
#pragma unroll
    for (int off = 16; off; off >>= 1) m = fmaxf(m, __shfl_xor_sync(0xFFFFFFFFu, m, off));
    if (lane == 0) outv[row] = m;
}

__global__ void bcast_add_kernel(const float* __restrict__ colm,
                                 const float* __restrict__ rowm,
                                 float* __restrict__ outp)
{
    size_t idx = (size_t)blockIdx.x * blockDim.x + threadIdx.x;
    if (idx >= SZ_MID) return;
    int    w  = (int)(idx % WW);
    size_t t  = idx / WW;
    int    h  = (int)(t % HH);
    size_t bc = t / HH;
    outp[idx] = colm[bc * WW + w] + rowm[bc * HH + h];
}

// ---------------- launch -----------------------------------------------------
extern "C" void kernel_launch(void* const* d_in, const int* in_sizes, int n_in,
                              void* d_out, int out_size)
{
    const float* x    = (const float*)d_in[0];
    const float* p1_w = (const float*)d_in[1];
    const float* p1_g = (const float*)d_in[2];
    const float* p1_b = (const float*)d_in[3];
    const float* p1_m = (const float*)d_in[4];
    const float* p1_v = (const float*)d_in[5];
    const float* p2_w = (const float*)d_in[6];
    const float* p2_g = (const float*)d_in[7];
    const float* p2_b = (const float*)d_in[8];
    const float* p2_m = (const float*)d_in[9];
    const float* p2_v = (const float*)d_in[10];
    const float* p_w  = (const float*)d_in[11];
    const float* p_g  = (const float*)d_in[12];
    const float* p_b  = (const float*)d_in[13];
    const float* p_m  = (const float*)d_in[14];
    const float* p_v  = (const float*)d_in[15];
    const float* c1_w = (const float*)d_in[16];
    const float* c1_g = (const float*)d_in[17];
    const float* c1_b = (const float*)d_in[18];
    const float* c1_m = (const float*)d_in[19];
    const float* c1_v = (const float*)d_in[20];
    const float* c2_w = (const float*)d_in[21];
    const float* c2_g = (const float*)d_in[22];
    const float* c2_b = (const float*)d_in[23];
    const float* c2_m = (const float*)d_in[24];
    const float* c2_v = (const float*)d_in[25];

    float *relu1, *relu2, *pool, *skip, *y, *colm, *rowm, *sc, *sh;
    float *wt1, *wt2, *wtp, *wtc1, *wtc2;
    cudaGetSymbolAddress((void**)&relu1, g_relu1);
    cudaGetSymbolAddress((void**)&relu2, g_relu2);
    cudaGetSymbolAddress((void**)&pool,  g_pool);
    cudaGetSymbolAddress((void**)&skip,  g_skip);
    cudaGetSymbolAddress((void**)&y,     g_y);
    cudaGetSymbolAddress((void**)&colm,  g_colmax);
    cudaGetSymbolAddress((void**)&rowm,  g_rowmax);
    cudaGetSymbolAddress((void**)&sc,    g_scale);
    cudaGetSymbolAddress((void**)&sh,    g_shift);
    cudaGetSymbolAddress((void**)&wt1,   g_wt1);
    cudaGetSymbolAddress((void**)&wt2,   g_wt2);
    cudaGetSymbolAddress((void**)&wtp,   g_wtp);
    cudaGetSymbolAddress((void**)&wtc1,  g_wtc1);
    cudaGetSymbolAddress((void**)&wtc2,  g_wtc2);

    // BN folds: offsets p1:0, p2:128, p:256, c1:512, c2:768
    bnprep_kernel<<<1, 128>>>(p1_g, p1_b, p1_m, p1_v, sc + 0,   sh + 0,   MID);
    bnprep_kernel<<<1, 128>>>(p2_g, p2_b, p2_m, p2_v, sc + 128, sh + 128, MID);
    bnprep_kernel<<<1, 256>>>(p_g,  p_b,  p_m,  p_v,  sc + 256, sh + 256, DIM);
    bnprep_kernel<<<1, 256>>>(c1_g, c1_b, c1_m, c1_v, sc + 512, sh + 512, DIM);
    bnprep_kernel<<<1, 256>>>(c2_g, c2_b, c2_m, c2_v, sc + 768, sh + 768, DIM);

    // weight transposes -> [k][ci][co]
    wtrans_kernel<<<512, 256>>>(p1_w, wt1,  MID, DIM, 9);
    wtrans_kernel<<<512, 256>>>(p2_w, wt2,  MID, DIM, 9);
    wtrans_kernel<<<512, 256>>>(p_w,  wtp,  DIM, MID, 9);
    wtrans_kernel<<<256, 256>>>(c1_w, wtc1, DIM, DIM, 1);
    wtrans_kernel<<<1024, 256>>>(c2_w, wtc2, DIM, DIM, 9);

    dim3 blk(256);
    dim3 g_mid(HH, MID / 128, BATCH);   // (128, 1, 4)
    dim3 g_dim(HH, DIM / 128, BATCH);   // (128, 2, 4)

    // branch convs (tf32 mma.sync)
    convmma_kernel<<<g_mid, blk>>>(x, DIM, wt1, 9, sc + 0,   sh + 0,   nullptr, relu1, MID, 1);
    convmma_kernel<<<g_mid, blk>>>(x, DIM, wt2, 9, sc + 128, sh + 128, nullptr, relu2, MID, 1);

    // composed directional pools == global max along H / W, broadcast-added
    colmax_kernel<<<(BATCH * MID * WW + 255) / 256, 256>>>(relu1, colm);
    rowmax_kernel<<<(BATCH * MID * HH) / 8, 256>>>(relu2, rowm);
    bcast_add_kernel<<<(unsigned)((SZ_MID + 255) / 256), 256>>>(colm, rowm, pool);

    // skip: 1x1 conv + BN
    convmma_kernel<<<g_dim, blk>>>(x, DIM, wtc1, 1, sc + 512, sh + 512, nullptr, skip, DIM, 0);

    // merge conv + BN + skip-add + ReLU
    convmma_kernel<<<g_dim, blk>>>(pool, MID, wtp, 9, sc + 256, sh + 256, skip, y, DIM, 1);

    // final conv + BN + ReLU -> output
    convmma_kernel<<<g_dim, blk>>>(y, DIM, wtc2, 9, sc + 768, sh + 768, nullptr, (float*)d_out, DIM, 1);
}

// round 10
// speedup vs baseline: 3.4205x; 1.0903x over previous
#include <cuda_runtime.h>
#include <math.h>
#include <stdint.h>

#define BATCH 4
#define DIM   256
#define MID   128
#define HH    128
#define WW    128
#define EPSV  1e-5f

// ---------------- scratch (device globals; no runtime allocation) ----------
static const size_t SZ_MID = (size_t)BATCH * MID * HH * WW;   // 8,388,608
static const size_t SZ_DIM = (size_t)BATCH * DIM * HH * WW;   // 16,777,216

__device__ float g_relu1[SZ_MID];
__device__ float g_relu2[SZ_MID];
__device__ float g_pool [SZ_MID];
__device__ float g_skip [SZ_DIM];
__device__ float g_y    [SZ_DIM];
__device__ float g_colmax[(size_t)BATCH * MID * WW];
__device__ float g_rowmax[(size_t)BATCH * MID * HH];
__device__ float g_scale[1024];
__device__ float g_shift[1024];
// transposed weights: [k][ci][co]
__device__ float g_wt1 [9 * MID * DIM];    // p1  [9][256][128]
__device__ float g_wt2 [9 * MID * DIM];    // p2
__device__ float g_wtp [9 * DIM * MID];    // merge [9][128][256]
__device__ float g_wtc1[DIM * DIM];        // skip 1x1 [1][256][256]
__device__ float g_wtc2[9 * DIM * DIM];    // final

// ---------------- helpers ----------------------------------------------------
__device__ __forceinline__ uint32_t tf32b(float x) {
    uint32_t r; asm("cvt.rn.tf32.f32 %0, %1;" : "=r"(r) : "f"(x)); return r;
}

__device__ __forceinline__ void mma_tf32(float* c, const uint32_t* a, const uint32_t* b) {
    asm volatile("mma.sync.aligned.m16n8k8.row.col.f32.tf32.tf32.f32 "
        "{%0,%1,%2,%3}, {%4,%5,%6,%7}, {%8,%9}, {%0,%1,%2,%3};"
        : "+f"(c[0]), "+f"(c[1]), "+f"(c[2]), "+f"(c[3])
        : "r"(a[0]), "r"(a[1]), "r"(a[2]), "r"(a[3]), "r"(b[0]), "r"(b[1]));
}

// smem row stride in floats: 136 (136 mod 32 == 8 -> fragment bank = (8r+g+c)
// mod 32, all 32 lanes distinct for every tile/base combination)
#define SSTR 136
#define A_TILE (32 * SSTR)                 // one 32ci x 128co tile (padded)
#define SMEM_FLOATS (3 * A_TILE + A_TILE)  // 3 A tiles + 1 B tile
#define SMEM_BYTES  (SMEM_FLOATS * 4)      // 69632

// ---------------- BN fold ---------------------------------------------------
__global__ void bnprep_kernel(const float* __restrict__ g, const float* __restrict__ b,
                              const float* __restrict__ m, const float* __restrict__ v,
                              float* __restrict__ sc, float* __restrict__ sh, int n)
{
    int i = blockIdx.x * blockDim.x + threadIdx.x;
    if (i < n) {
        float inv = rsqrtf(v[i] + EPSV);
        float s = g[i] * inv;
        sc[i] = s;
        sh[i] = b[i] - m[i] * s;
    }
}

// ------------- weight transpose: [CO,CI,KK] view -> [k][ci][co] -------------
__global__ void wtrans_kernel(const float* __restrict__ w, float* __restrict__ wt,
                              int COUT, int CIN, int KK)
{
    size_t n = (size_t)COUT * CIN * KK;
    for (size_t o = (size_t)blockIdx.x * blockDim.x + threadIdx.x; o < n;
         o += (size_t)gridDim.x * blockDim.x) {
        int co = (int)(o % COUT);
        size_t t = o / COUT;
        int ci = (int)(t % CIN);
        int k  = (int)(t / CIN);
        wt[o] = w[((size_t)co * CIN + ci) * KK + k];
    }
}

// ---------------- tf32 mma.sync implicit-GEMM conv --------------------------
// CTA: 128 co x 128 px (one output image row). 256 threads.
// Unit of work: (32-ci block, input row yy). B row loaded ONCE, then the 3
// horizontal taps run as 3 MMA sweeps with shifted B base (pad cols are zero).
__global__ __launch_bounds__(256, 2)
void convmma_kernel(const float* __restrict__ in, int CIN,
                    const float* __restrict__ wtT, int KK,      // 9 or 1
                    const float* __restrict__ scale,
                    const float* __restrict__ shift,
                    const float* __restrict__ skip,             // may be null
                    float* __restrict__ out, int COUT, int do_relu)
{
    extern __shared__ float smem[];
    float* sA = smem;                 // 3 tiles of [32][136]
    float* sB = smem + 3 * A_TILE;    // [32ci][136]: data at cols 1..128, pads 0

    const int tid  = threadIdx.x;
    const int wid  = tid >> 5;
    const int lane = tid & 31;
    const int y       = blockIdx.x;
    const int co_base = blockIdx.y * 128;
    const int b       = blockIdx.z;
    const int nCB  = CIN / 32;
    const int ndy  = (KK == 9) ? 3 : 1;
    const int ntap = (KK == 9) ? 3 : 1;

    const int wm = wid & 1;    // 0..1 -> co half (64)
    const int wn = wid >> 1;   // 0..3 -> px quarter (32)

    // zero B pad columns (cols 0 and 129..135) once; never overwritten after
    {
        const int row  = tid >> 3;
        const int col8 = tid & 7;
        const int col  = (col8 == 0) ? 0 : (128 + col8);  // 0, 129..135
        sB[row * SSTR + col] = 0.f;
    }

    float acc[4][4][4];
#pragma unroll
    for (int i = 0; i < 4; i++)
#pragma unroll
        for (int j = 0; j < 4; j++)
#pragma unroll
            for (int q = 0; q < 4; q++) acc[i][j][q] = 0.f;

    const size_t cstr = (size_t)HH * WW;

    for (int cb = 0; cb < nCB; cb++) {
        for (int idy = 0; idy < ndy; idy++) {
            const int yy = (KK == 9) ? (y + idy - 1) : y;
            if (yy < 0 || yy >= HH) continue;   // whole row contributes zero

            __syncthreads();   // previous unit fully consumed

            if (tid < 128) {
                // B: actual input row (no shift, no predication)
                const int px = tid;
                const float* src = in + (((size_t)b * CIN + cb * 32) * HH + yy) * WW + px;
                uint32_t* dst = (uint32_t*)sB + px + 1;
#pragma unroll
                for (int c = 0; c < 32; c++)
                    dst[c * SSTR] = tf32b(src[(size_t)c * cstr]);
            } else {
                // A: the (up to) 3 horizontal-tap weight tiles for this dy
                const int u   = tid - 128;
                const int ci  = u >> 2;
                const int coq = (u & 3) * 32;
                for (int t3 = 0; t3 < ntap; t3++) {
                    const int k = (KK == 9) ? (idy * 3 + t3) : 0;
                    const float* wr = wtT + ((size_t)k * CIN + cb * 32 + ci) * COUT
                                    + co_base + coq;
                    uint32_t* dst = (uint32_t*)sA + t3 * A_TILE + ci * SSTR + coq;
#pragma unroll
                    for (int j = 0; j < 8; j++) {
                        float4 f = *(const float4*)(wr + j * 4);
                        dst[j * 4 + 0] = tf32b(f.x);
                        dst[j * 4 + 1] = tf32b(f.y);
                        dst[j * 4 + 2] = tf32b(f.z);
                        dst[j * 4 + 3] = tf32b(f.w);
                    }
                }
            }
            __syncthreads();

            // consume: 3 taps x 4 k-steps of m16n8k8
            for (int t3 = 0; t3 < ntap; t3++) {
                const uint32_t* tA = (const uint32_t*)sA + t3 * A_TILE;
                const int bbase = (KK == 9) ? t3 : 1;   // dx = t3-1 -> col off
#pragma unroll
                for (int ks = 0; ks < 4; ks++) {
                    const int k0 = ks * 8 + (lane & 3);
                    const uint32_t* pa0 = tA + k0 * SSTR;
                    const uint32_t* pa4 = pa0 + 4 * SSTR;
                    const uint32_t* pb0 = (const uint32_t*)sB + k0 * SSTR + bbase;
                    const uint32_t* pb4 = pb0 + 4 * SSTR;

                    uint32_t af[4][4], bf[4][2];
#pragma unroll
                    for (int mt = 0; mt < 4; mt++) {
                        const int r0 = wm * 64 + mt * 16 + (lane >> 2);
                        af[mt][0] = pa0[r0];
                        af[mt][1] = pa0[r0 + 8];
                        af[mt][2] = pa4[r0];
                        af[mt][3] = pa4[r0 + 8];
                    }
#pragma unroll
                    for (int nt = 0; nt < 4; nt++) {
                        const int c0 = wn * 32 + nt * 8 + (lane >> 2);
                        bf[nt][0] = pb0[c0];
                        bf[nt][1] = pb4[c0];
                    }
#pragma unroll
                    for (int mt = 0; mt < 4; mt++)
#pragma unroll
                        for (int nt = 0; nt < 4; nt++)
                            mma_tf32(acc[mt][nt], af[mt], bf[nt]);
                }
            }
        }
    }

    // epilogue: BN (+skip) (+relu), direct register write-out
#pragma unroll
    for (int mt = 0; mt < 4; mt++) {
        const int r0 = co_base + wm * 64 + mt * 16 + (lane >> 2);
        const int r1 = r0 + 8;
        const float sc0 = scale[r0], sh0 = shift[r0];
        const float sc1 = scale[r1], sh1 = shift[r1];
        const size_t ob0 = ((size_t)(b * COUT + r0) * HH + y) * WW;
        const size_t ob1 = ((size_t)(b * COUT + r1) * HH + y) * WW;
#pragma unroll
        for (int nt = 0; nt < 4; nt++) {
            const int c = wn * 32 + nt * 8 + 2 * (lane & 3);
            float2 v0, v1;
            v0.x = acc[mt][nt][0] * sc0 + sh0;
            v0.y = acc[mt][nt][1] * sc0 + sh0;
            v1.x = acc[mt][nt][2] * sc1 + sh1;
            v1.y = acc[mt][nt][3] * sc1 + sh1;
            if (skip) {
                float2 s0 = *(const float2*)(skip + ob0 + c);
                float2 s1 = *(const float2*)(skip + ob1 + c);
                v0.x += s0.x; v0.y += s0.y;
                v1.x += s1.x; v1.y += s1.y;
            }
            if (do_relu) {
                v0.x = fmaxf(v0.x, 0.f); v0.y = fmaxf(v0.y, 0.f);
                v1.x = fmaxf(v1.x, 0.f); v1.y = fmaxf(v1.y, 0.f);
            }
            *(float2*)(out + ob0 + c) = v0;
            *(float2*)(out + ob1 + c) = v1;
        }
    }
}

// ---------------- pools: composed cummax pairs == global max broadcast ------
__global__ void colmax_kernel(const float* __restrict__ in, float* __restrict__ outv)
{
    int idx = blockIdx.x * blockDim.x + threadIdx.x;
    if (idx >= BATCH * MID * WW) return;
    int w  = idx % WW;
    int bc = idx / WW;
    const float* p = in + (size_t)bc * HH * WW + w;
    float m = -INFINITY;
#pragma unroll 4
    for (int h = 0; h < HH; h++) m = fmaxf(m, p[(size_t)h * WW]);
    outv[idx] = m;
}

__global__ void rowmax_kernel(const float* __restrict__ in, float* __restrict__ outv)
{
    int row  = blockIdx.x * (blockDim.x / 32) + (threadIdx.x >> 5);
    int lane = threadIdx.x & 31;
    if (row >= BATCH * MID * HH) return;
    const float* p = in + (size_t)row * WW;
    float m = -INFINITY;
    for (int w = lane; w < WW; w += 32) m = fmaxf(m, p[w]);
#pragma unroll
    for (int off = 16; off; off >>= 1) m = fmaxf(m, __shfl_xor_sync(0xFFFFFFFFu, m, off));
    if (lane == 0) outv[row] = m;
}

__global__ void bcast_add_kernel(const float* __restrict__ colm,
                                 const float* __restrict__ rowm,
                                 float* __restrict__ outp)
{
    size_t idx = (size_t)blockIdx.x * blockDim.x + threadIdx.x;
    if (idx >= SZ_MID) return;
    int    w  = (int)(idx % WW);
    size_t t  = idx / WW;
    int    h  = (int)(t % HH);
    size_t bc = t / HH;
    outp[idx] = colm[bc * WW + w] + rowm[bc * HH + h];
}

// ---------------- launch -----------------------------------------------------
extern "C" void kernel_launch(void* const* d_in, const int* in_sizes, int n_in,
                              void* d_out, int out_size)
{
    const float* x    = (const float*)d_in[0];
    const float* p1_w = (const float*)d_in[1];
    const float* p1_g = (const float*)d_in[2];
    const float* p1_b = (const float*)d_in[3];
    const float* p1_m = (const float*)d_in[4];
    const float* p1_v = (const float*)d_in[5];
    const float* p2_w = (const float*)d_in[6];
    const float* p2_g = (const float*)d_in[7];
    const float* p2_b = (const float*)d_in[8];
    const float* p2_m = (const float*)d_in[9];
    const float* p2_v = (const float*)d_in[10];
    const float* p_w  = (const float*)d_in[11];
    const float* p_g  = (const float*)d_in[12];
    const float* p_b  = (const float*)d_in[13];
    const float* p_m  = (const float*)d_in[14];
    const float* p_v  = (const float*)d_in[15];
    const float* c1_w = (const float*)d_in[16];
    const float* c1_g = (const float*)d_in[17];
    const float* c1_b = (const float*)d_in[18];
    const float* c1_m = (const float*)d_in[19];
    const float* c1_v = (const float*)d_in[20];
    const float* c2_w = (const float*)d_in[21];
    const float* c2_g = (const float*)d_in[22];
    const float* c2_b = (const float*)d_in[23];
    const float* c2_m = (const float*)d_in[24];
    const float* c2_v = (const float*)d_in[25];

    float *relu1, *relu2, *pool, *skip, *y, *colm, *rowm, *sc, *sh;
    float *wt1, *wt2, *wtp, *wtc1, *wtc2;
    cudaGetSymbolAddress((void**)&relu1, g_relu1);
    cudaGetSymbolAddress((void**)&relu2, g_relu2);
    cudaGetSymbolAddress((void**)&pool,  g_pool);
    cudaGetSymbolAddress((void**)&skip,  g_skip);
    cudaGetSymbolAddress((void**)&y,     g_y);
    cudaGetSymbolAddress((void**)&colm,  g_colmax);
    cudaGetSymbolAddress((void**)&rowm,  g_rowmax);
    cudaGetSymbolAddress((void**)&sc,    g_scale);
    cudaGetSymbolAddress((void**)&sh,    g_shift);
    cudaGetSymbolAddress((void**)&wt1,   g_wt1);
    cudaGetSymbolAddress((void**)&wt2,   g_wt2);
    cudaGetSymbolAddress((void**)&wtp,   g_wtp);
    cudaGetSymbolAddress((void**)&wtc1,  g_wtc1);
    cudaGetSymbolAddress((void**)&wtc2,  g_wtc2);

    cudaFuncSetAttribute(convmma_kernel,
                         cudaFuncAttributeMaxDynamicSharedMemorySize, SMEM_BYTES);

    // BN folds: offsets p1:0, p2:128, p:256, c1:512, c2:768
    bnprep_kernel<<<1, 128>>>(p1_g, p1_b, p1_m, p1_v, sc + 0,   sh + 0,   MID);
    bnprep_kernel<<<1, 128>>>(p2_g, p2_b, p2_m, p2_v, sc + 128, sh + 128, MID);
    bnprep_kernel<<<1, 256>>>(p_g,  p_b,  p_m,  p_v,  sc + 256, sh + 256, DIM);
    bnprep_kernel<<<1, 256>>>(c1_g, c1_b, c1_m, c1_v, sc + 512, sh + 512, DIM);
    bnprep_kernel<<<1, 256>>>(c2_g, c2_b, c2_m, c2_v, sc + 768, sh + 768, DIM);

    // weight transposes -> [k][ci][co]
    wtrans_kernel<<<512, 256>>>(p1_w, wt1,  MID, DIM, 9);
    wtrans_kernel<<<512, 256>>>(p2_w, wt2,  MID, DIM, 9);
    wtrans_kernel<<<512, 256>>>(p_w,  wtp,  DIM, MID, 9);
    wtrans_kernel<<<256, 256>>>(c1_w, wtc1, DIM, DIM, 1);
    wtrans_kernel<<<1024, 256>>>(c2_w, wtc2, DIM, DIM, 9);

    dim3 blk(256);
    dim3 g_mid(HH, MID / 128, BATCH);   // (128, 1, 4)
    dim3 g_dim(HH, DIM / 128, BATCH);   // (128, 2, 4)

    // branch convs (tf32 mma.sync)
    convmma_kernel<<<g_mid, blk, SMEM_BYTES>>>(x, DIM, wt1, 9, sc + 0,   sh + 0,   nullptr, relu1, MID, 1);
    convmma_kernel<<<g_mid, blk, SMEM_BYTES>>>(x, DIM, wt2, 9, sc + 128, sh + 128, nullptr, relu2, MID, 1);

    // composed directional pools == global max along H / W, broadcast-added
    colmax_kernel<<<(BATCH * MID * WW + 255) / 256, 256>>>(relu1, colm);
    rowmax_kernel<<<(BATCH * MID * HH) / 8, 256>>>(relu2, rowm);
    bcast_add_kernel<<<(unsigned)((SZ_MID + 255) / 256), 256>>>(colm, rowm, pool);

    // skip: 1x1 conv + BN
    convmma_kernel<<<g_dim, blk, SMEM_BYTES>>>(x, DIM, wtc1, 1, sc + 512, sh + 512, nullptr, skip, DIM, 0);

    // merge conv + BN + skip-add + ReLU
    convmma_kernel<<<g_dim, blk, SMEM_BYTES>>>(pool, MID, wtp, 9, sc + 256, sh + 256, skip, y, DIM, 1);

    // final conv + BN + ReLU -> output
    convmma_kernel<<<g_dim, blk, SMEM_BYTES>>>(y, DIM, wtc2, 9, sc + 768, sh + 768, nullptr, (float*)d_out, DIM, 1);
}

// round 12
// speedup vs baseline: 6.9516x; 2.0323x over previous
#include <cuda_runtime.h>
#include <cuda_fp16.h>
#include <math.h>
#include <stdint.h>

#define BATCH 4
#define DIM   256
#define MID   128
#define HH    128
#define WW    128
#define EPSV  1e-5f

// ---------------- scratch (device globals; no runtime allocation) ----------
static const size_t SZ_MID = (size_t)BATCH * MID * HH * WW;   // 8,388,608
static const size_t SZ_DIM = (size_t)BATCH * DIM * HH * WW;   // 16,777,216

__device__ float g_relu1[SZ_MID];
__device__ float g_relu2[SZ_MID];
__device__ float g_pool [SZ_MID];
__device__ float g_skip [SZ_DIM];
__device__ float g_y    [SZ_DIM];
__device__ float g_colmax[(size_t)BATCH * MID * WW];
__device__ float g_rowmax[(size_t)BATCH * MID * HH];
__device__ float g_scale[1024];
__device__ float g_shift[1024];
// half weights, layout [k][co][ci] (ci contiguous), 16B-aligned for uint4 IO
__device__ __align__(16) __half g_wt1 [9 * MID * DIM];    // p1  [9][128][256]
__device__ __align__(16) __half g_wt2 [9 * MID * DIM];    // p2
__device__ __align__(16) __half g_wtp [9 * DIM * MID];    // merge [9][256][128]
__device__ __align__(16) __half g_wtc1[DIM * DIM];        // skip 1x1 [1][256][256]
__device__ __align__(16) __half g_wtc2[9 * DIM * DIM];    // final

// ---------------- helpers ----------------------------------------------------
__device__ __forceinline__ void mma_f16(float* c, const uint32_t* a, const uint32_t* b) {
    asm volatile("mma.sync.aligned.m16n8k16.row.col.f32.f16.f16.f32 "
        "{%0,%1,%2,%3}, {%4,%5,%6,%7}, {%8,%9}, {%0,%1,%2,%3};"
        : "+f"(c[0]), "+f"(c[1]), "+f"(c[2]), "+f"(c[3])
        : "r"(a[0]), "r"(a[1]), "r"(a[2]), "r"(a[3]), "r"(b[0]), "r"(b[1]));
}

// row stride 20 words (40 halfs, 80B): bank = (20*row + word) mod 32 spans all
// 32 banks for every fragment access pattern (q=row 0..7, word g / g+4 ...).
#define STRW 20
#define A_TILE_W (128 * STRW)          // one 128co x 32ci half tile, in words
#define B_TILE_W (130 * STRW)          // 130 px rows (pad rows 0 and 129)
#define SMEM_WORDS (3 * A_TILE_W + B_TILE_W)   // 10280 words = 41120 B

// ---------------- BN fold ---------------------------------------------------
__global__ void bnprep_kernel(const float* __restrict__ g, const float* __restrict__ b,
                              const float* __restrict__ m, const float* __restrict__ v,
                              float* __restrict__ sc, float* __restrict__ sh, int n)
{
    int i = blockIdx.x * blockDim.x + threadIdx.x;
    if (i < n) {
        float inv = rsqrtf(v[i] + EPSV);
        float s = g[i] * inv;
        sc[i] = s;
        sh[i] = b[i] - m[i] * s;
    }
}

// ------- weight transform: [CO,CI,KK] float -> [k][co][ci] half -------------
__global__ void wtrans_kernel(const float* __restrict__ w, __half* __restrict__ wt,
                              int COUT, int CIN, int KK)
{
    size_t n = (size_t)COUT * CIN * KK;
    for (size_t o = (size_t)blockIdx.x * blockDim.x + threadIdx.x; o < n;
         o += (size_t)gridDim.x * blockDim.x) {
        int ci = (int)(o % CIN);
        size_t t = o / CIN;
        int co = (int)(t % COUT);
        int k  = (int)(t / COUT);
        wt[o] = __float2half(w[((size_t)co * CIN + ci) * KK + k]);
    }
}

// ---------------- fp16 mma.sync implicit-GEMM conv --------------------------
// CTA: 128 co x 128 px (one output image row). 256 threads.
// Unit of work: (32-ci block, input row yy). B row loaded ONCE into
// [px_row][ci] half tile; the 3 horizontal taps are row offsets on B.
__global__ __launch_bounds__(256, 2)
void convmma_kernel(const float* __restrict__ in, int CIN,
                    const __half* __restrict__ wtT, int KK,     // 9 or 1
                    const float* __restrict__ scale,
                    const float* __restrict__ shift,
                    const float* __restrict__ skip,             // may be null
                    float* __restrict__ out, int COUT, int do_relu)
{
    __shared__ __align__(16) uint32_t smw[SMEM_WORDS];
    uint32_t* sA = smw;                  // 3 tiles [128co][STRW]
    uint32_t* sB = smw + 3 * A_TILE_W;   // [130px][STRW], data rows 1..128

    const int tid  = threadIdx.x;
    const int wid  = tid >> 5;
    const int lane = tid & 31;
    const int y       = blockIdx.x;
    const int co_base = blockIdx.y * 128;
    const int b       = blockIdx.z;
    const int nCB  = CIN / 32;
    const int ndy  = (KK == 9) ? 3 : 1;
    const int ntap = (KK == 9) ? 3 : 1;

    const int wm = wid & 1;    // co half (64)
    const int wn = wid >> 1;   // px quarter (32)
    const int q  = lane >> 2;
    const int g  = lane & 3;

    // zero B pad rows (px_row 0 and 129), 40 words total
    if (tid < 2 * STRW) {
        const int r   = (tid < STRW) ? 0 : 129;
        const int col = (tid < STRW) ? tid : (tid - STRW);
        sB[r * STRW + col] = 0u;
    }

    float acc[4][4][4];
#pragma unroll
    for (int i = 0; i < 4; i++)
#pragma unroll
        for (int j = 0; j < 4; j++)
#pragma unroll
            for (int p = 0; p < 4; p++) acc[i][j][p] = 0.f;

    const size_t cstr = (size_t)HH * WW;

    for (int cb = 0; cb < nCB; cb++) {
        for (int idy = 0; idy < ndy; idy++) {
            const int yy = (KK == 9) ? (y + idy - 1) : y;
            if (yy < 0 || yy >= HH) continue;   // whole row contributes zero

            __syncthreads();   // previous unit fully consumed

            if (tid < 128) {
                // B: input row px=tid, 32 ci values -> 16 half2 words
                const int px = tid;
                const float* src = in + (((size_t)b * CIN + cb * 32) * HH + yy) * WW + px;
                uint32_t* dst = sB + (px + 1) * STRW;
#pragma unroll
                for (int c2 = 0; c2 < 16; c2++) {
                    float f0 = src[(size_t)(2 * c2)     * cstr];
                    float f1 = src[(size_t)(2 * c2 + 1) * cstr];
                    __half2 h = __floats2half2_rn(f0, f1);
                    dst[c2] = *(const uint32_t*)&h;
                }
            } else {
                // A: one co row (32 halfs = 4 x uint4 = 16 words) per tap
                const int u = tid - 128;   // co row 0..127
                for (int t3 = 0; t3 < ntap; t3++) {
                    const int k = (KK == 9) ? (idy * 3 + t3) : 0;
                    const __half* wr = wtT + ((size_t)k * COUT + co_base + u) * CIN + cb * 32;
                    const uint4 w0 = ((const uint4*)wr)[0];
                    const uint4 w1 = ((const uint4*)wr)[1];
                    const uint4 w2 = ((const uint4*)wr)[2];
                    const uint4 w3 = ((const uint4*)wr)[3];
                    uint4* dst = (uint4*)(sA + t3 * A_TILE_W + u * STRW);
                    dst[0] = w0;
                    dst[1] = w1;
                    dst[2] = w2;
                    dst[3] = w3;
                }
            }
            __syncthreads();

            // consume: ntap x 2 k-steps of m16n8k16
            for (int t3 = 0; t3 < ntap; t3++) {
                const uint32_t* tA = sA + t3 * A_TILE_W;
                const int bbase = (KK == 9) ? t3 : 1;   // px row offset (dx+1)
#pragma unroll
                for (int ks = 0; ks < 2; ks++) {
                    const int kw = ks * 8 + g;          // half2 word in row
                    uint32_t af[4][4], bf[4][2];
#pragma unroll
                    for (int mt = 0; mt < 4; mt++) {
                        const int r0 = wm * 64 + mt * 16 + q;
                        af[mt][0] = tA[r0 * STRW + kw];
                        af[mt][1] = tA[(r0 + 8) * STRW + kw];
                        af[mt][2] = tA[r0 * STRW + kw + 4];
                        af[mt][3] = tA[(r0 + 8) * STRW + kw + 4];
                    }
#pragma unroll
                    for (int nt = 0; nt < 4; nt++) {
                        const int pr = wn * 32 + nt * 8 + q + bbase;
                        bf[nt][0] = sB[pr * STRW + kw];
                        bf[nt][1] = sB[pr * STRW + kw + 4];
                    }
#pragma unroll
                    for (int mt = 0; mt < 4; mt++)
#pragma unroll
                        for (int nt = 0; nt < 4; nt++)
                            mma_f16(acc[mt][nt], af[mt], bf[nt]);
                }
            }
        }
    }

    // epilogue: BN (+skip) (+relu), direct register write-out
#pragma unroll
    for (int mt = 0; mt < 4; mt++) {
        const int r0 = co_base + wm * 64 + mt * 16 + q;
        const int r1 = r0 + 8;
        const float sc0 = scale[r0], sh0 = shift[r0];
        const float sc1 = scale[r1], sh1 = shift[r1];
        const size_t ob0 = ((size_t)(b * COUT + r0) * HH + y) * WW;
        const size_t ob1 = ((size_t)(b * COUT + r1) * HH + y) * WW;
#pragma unroll
        for (int nt = 0; nt < 4; nt++) {
            const int c = wn * 32 + nt * 8 + 2 * g;
            float2 v0, v1;
            v0.x = acc[mt][nt][0] * sc0 + sh0;
            v0.y = acc[mt][nt][1] * sc0 + sh0;
            v1.x = acc[mt][nt][2] * sc1 + sh1;
            v1.y = acc[mt][nt][3] * sc1 + sh1;
            if (skip) {
                float2 s0 = *(const float2*)(skip + ob0 + c);
                float2 s1 = *(const float2*)(skip + ob1 + c);
                v0.x += s0.x; v0.y += s0.y;
                v1.x += s1.x; v1.y += s1.y;
            }
            if (do_relu) {
                v0.x = fmaxf(v0.x, 0.f); v0.y = fmaxf(v0.y, 0.f);
                v1.x = fmaxf(v1.x, 0.f); v1.y = fmaxf(v1.y, 0.f);
            }
            *(float2*)(out + ob0 + c) = v0;
            *(float2*)(out + ob1 + c) = v1;
        }
    }
}

// ---------------- pools: composed cummax pairs == global max broadcast ------
__global__ void colmax_kernel(const float* __restrict__ in, float* __restrict__ outv)
{
    int idx = blockIdx.x * blockDim.x + threadIdx.x;
    if (idx >= BATCH * MID * WW) return;
    int w  = idx % WW;
    int bc = idx / WW;
    const float* p = in + (size_t)bc * HH * WW + w;
    float m = -INFINITY;
#pragma unroll 4
    for (int h = 0; h < HH; h++) m = fmaxf(m, p[(size_t)h * WW]);
    outv[idx] = m;
}

__global__ void rowmax_kernel(const float* __restrict__ in, float* __restrict__ outv)
{
    int row  = blockIdx.x * (blockDim.x / 32) + (threadIdx.x >> 5);
    int lane = threadIdx.x & 31;
    if (row >= BATCH * MID * HH) return;
    const float* p = in + (size_t)row * WW;
    float m = -INFINITY;
    for (int w = lane; w < WW; w += 32) m = fmaxf(m, p[w]);
#pragma unroll
    for (int off = 16; off; off >>= 1) m = fmaxf(m, __shfl_xor_sync(0xFFFFFFFFu, m, off));
    if (lane == 0) outv[row] = m;
}

__global__ void bcast_add_kernel(const float* __restrict__ colm,
                                 const float* __restrict__ rowm,
                                 float* __restrict__ outp)
{
    size_t idx = (size_t)blockIdx.x * blockDim.x + threadIdx.x;
    if (idx >= SZ_MID) return;
    int    w  = (int)(idx % WW);
    size_t t  = idx / WW;
    int    h  = (int)(t % HH);
    size_t bc = t / HH;
    outp[idx] = colm[bc * WW + w] + rowm[bc * HH + h];
}

// ---------------- launch -----------------------------------------------------
extern "C" void kernel_launch(void* const* d_in, const int* in_sizes, int n_in,
                              void* d_out, int out_size)
{
    const float* x    = (const float*)d_in[0];
    const float* p1_w = (const float*)d_in[1];
    const float* p1_g = (const float*)d_in[2];
    const float* p1_b = (const float*)d_in[3];
    const float* p1_m = (const float*)d_in[4];
    const float* p1_v = (const float*)d_in[5];
    const float* p2_w = (const float*)d_in[6];
    const float* p2_g = (const float*)d_in[7];
    const float* p2_b = (const float*)d_in[8];
    const float* p2_m = (const float*)d_in[9];
    const float* p2_v = (const float*)d_in[10];
    const float* p_w  = (const float*)d_in[11];
    const float* p_g  = (const float*)d_in[12];
    const float* p_b  = (const float*)d_in[13];
    const float* p_m  = (const float*)d_in[14];
    const float* p_v  = (const float*)d_in[15];
    const float* c1_w = (const float*)d_in[16];
    const float* c1_g = (const float*)d_in[17];
    const float* c1_b = (const float*)d_in[18];
    const float* c1_m = (const float*)d_in[19];
    const float* c1_v = (const float*)d_in[20];
    const float* c2_w = (const float*)d_in[21];
    const float* c2_g = (const float*)d_in[22];
    const float* c2_b = (const float*)d_in[23];
    const float* c2_m = (const float*)d_in[24];
    const float* c2_v = (const float*)d_in[25];

    float *relu1, *relu2, *pool, *skip, *y, *colm, *rowm, *sc, *sh;
    __half *wt1, *wt2, *wtp, *wtc1, *wtc2;
    cudaGetSymbolAddress((void**)&relu1, g_relu1);
    cudaGetSymbolAddress((void**)&relu2, g_relu2);
    cudaGetSymbolAddress((void**)&pool,  g_pool);
    cudaGetSymbolAddress((void**)&skip,  g_skip);
    cudaGetSymbolAddress((void**)&y,     g_y);
    cudaGetSymbolAddress((void**)&colm,  g_colmax);
    cudaGetSymbolAddress((void**)&rowm,  g_rowmax);
    cudaGetSymbolAddress((void**)&sc,    g_scale);
    cudaGetSymbolAddress((void**)&sh,    g_shift);
    cudaGetSymbolAddress((void**)&wt1,   g_wt1);
    cudaGetSymbolAddress((void**)&wt2,   g_wt2);
    cudaGetSymbolAddress((void**)&wtp,   g_wtp);
    cudaGetSymbolAddress((void**)&wtc1,  g_wtc1);
    cudaGetSymbolAddress((void**)&wtc2,  g_wtc2);

    // BN folds: offsets p1:0, p2:128, p:256, c1:512, c2:768
    bnprep_kernel<<<1, 128>>>(p1_g, p1_b, p1_m, p1_v, sc + 0,   sh + 0,   MID);
    bnprep_kernel<<<1, 128>>>(p2_g, p2_b, p2_m, p2_v, sc + 128, sh + 128, MID);
    bnprep_kernel<<<1, 256>>>(p_g,  p_b,  p_m,  p_v,  sc + 256, sh + 256, DIM);
    bnprep_kernel<<<1, 256>>>(c1_g, c1_b, c1_m, c1_v, sc + 512, sh + 512, DIM);
    bnprep_kernel<<<1, 256>>>(c2_g, c2_b, c2_m, c2_v, sc + 768, sh + 768, DIM);

    // weight transforms -> [k][co][ci] half
    wtrans_kernel<<<512, 256>>>(p1_w, wt1,  MID, DIM, 9);
    wtrans_kernel<<<512, 256>>>(p2_w, wt2,  MID, DIM, 9);
    wtrans_kernel<<<512, 256>>>(p_w,  wtp,  DIM, MID, 9);
    wtrans_kernel<<<256, 256>>>(c1_w, wtc1, DIM, DIM, 1);
    wtrans_kernel<<<1024, 256>>>(c2_w, wtc2, DIM, DIM, 9);

    dim3 blk(256);
    dim3 g_mid(HH, MID / 128, BATCH);   // (128, 1, 4)
    dim3 g_dim(HH, DIM / 128, BATCH);   // (128, 2, 4)

    // branch convs (fp16 mma.sync, fp32 accumulate)
    convmma_kernel<<<g_mid, blk>>>(x, DIM, wt1, 9, sc + 0,   sh + 0,   nullptr, relu1, MID, 1);
    convmma_kernel<<<g_mid, blk>>>(x, DIM, wt2, 9, sc + 128, sh + 128, nullptr, relu2, MID, 1);

    // composed directional pools == global max along H / W, broadcast-added
    colmax_kernel<<<(BATCH * MID * WW + 255) / 256, 256>>>(relu1, colm);
    rowmax_kernel<<<(BATCH * MID * HH) / 8, 256>>>(relu2, rowm);
    bcast_add_kernel<<<(unsigned)((SZ_MID + 255) / 256), 256>>>(colm, rowm, pool);

    // skip: 1x1 conv + BN
    convmma_kernel<<<g_dim, blk>>>(x, DIM, wtc1, 1, sc + 512, sh + 512, nullptr, skip, DIM, 0);

    // merge conv + BN + skip-add + ReLU
    convmma_kernel<<<g_dim, blk>>>(pool, MID, wtp, 9, sc + 256, sh + 256, skip, y, DIM, 1);

    // final conv + BN + ReLU -> output
    convmma_kernel<<<g_dim, blk>>>(y, DIM, wtc2, 9, sc + 768, sh + 768, nullptr, (float*)d_out, DIM, 1);
}